// round 3
// baseline (speedup 1.0000x reference)
#include <cuda_runtime.h>
#include <cuda_bf16.h>
#include <math.h>

// Problem constants (from reference): N=100000, D=128, C=1024, NUM_NODES=1e6.
#define MAX_N     100000
#define MAX_NODES 1000000
#define NCB       8            // number of column blocks (C / BN)

// Device scratch (no allocs allowed). NO 64-bit atomics (sm_103a trap risk).
__device__ unsigned long long g_cand[(size_t)(MAX_N + 128) * NCB];
__device__ int   g_winner[MAX_NODES];
__device__ float g_rn[MAX_N];
__device__ float g_cn[2048];

// ---------------------------------------------------------------------------
__global__ void clear_kernel(int m) {
    int i = blockIdx.x * blockDim.x + threadIdx.x;
    if (i < m) g_winner[i] = -1;
}

// One warp per row: sum of squares.
__global__ void rownorm_kernel(const float* __restrict__ X, int n, int D, int is_col) {
    int warp = (blockIdx.x * blockDim.x + threadIdx.x) >> 5;
    int lane = threadIdx.x & 31;
    if (warp >= n) return;
    const float* row = X + (size_t)warp * D;
    float s = 0.f;
    for (int k = lane; k < D; k += 32) { float v = row[k]; s += v * v; }
    #pragma unroll
    for (int o = 16; o; o >>= 1) s += __shfl_xor_sync(0xFFFFFFFFu, s, o);
    if (lane == 0) { if (is_col) g_cn[warp] = s; else g_rn[warp] = s; }
}

// Copy node state tables into output (as float32).
__global__ void copy_tables_kernel(const int* __restrict__ node_cell,
                                   const float* __restrict__ node_time,
                                   float* __restrict__ out_ncell,
                                   float* __restrict__ out_ntime, int m) {
    int j = blockIdx.x * blockDim.x + threadIdx.x;
    if (j < m) {
        if (out_ncell) out_ncell[j] = (float)node_cell[j];
        if (out_ntime) out_ntime[j] = node_time[j];
    }
}

// Last-write-wins resolution over duplicate node ids. nodes = INT32 (jax
// demotes int64->int32). Bounds-guarded: never trap on bad indices.
__global__ void winner_kernel(const int* __restrict__ nodes, int n, int m) {
    int i = blockIdx.x * blockDim.x + threadIdx.x;
    if (i >= n) return;
    int nd = nodes[i];
    if (nd >= 0 && nd < m) atomicMax(&g_winner[nd], i);
}

// ---------------------------------------------------------------------------
// Tiled fp32 GEMM + distance epilogue + atomic-free per-row argmin reduction.
#define BM 128
#define BN 128
#define BK 8

__global__ __launch_bounds__(256)
void gemm_dist_kernel(const float* __restrict__ A,   // [N, D] embeddings
                      const float* __restrict__ B,   // [C, D] memory map
                      float* __restrict__ out,       // [N, C] distances (may be null)
                      int N, int C, int D) {
    __shared__ float As[BK][BM];
    __shared__ float Bs[BK][BN];
    __shared__ unsigned long long best_sh[BM][16];

    const int tid  = threadIdx.x;
    const int brow = blockIdx.y * BM;
    const int bcol = blockIdx.x * BN;

    const int lr = tid >> 1;          // 0..127
    const int lk = (tid & 1) * 4;     // 0 or 4

    const int trow = (tid >> 4) * 8;
    const int tcol = (tid & 15) * 8;

    float acc[8][8];
    #pragma unroll
    for (int i = 0; i < 8; i++)
        #pragma unroll
        for (int j = 0; j < 8; j++) acc[i][j] = 0.f;

    const int ga = min(brow + lr, N - 1);          // clamp OOB rows
    const int gb = bcol + lr;                      // C divisible by 128

    for (int k0 = 0; k0 < D; k0 += BK) {
        float4 av = *(const float4*)(A + (size_t)ga * D + k0 + lk);
        float4 bv = *(const float4*)(B + (size_t)gb * D + k0 + lk);
        __syncthreads();
        As[lk + 0][lr] = av.x; As[lk + 1][lr] = av.y;
        As[lk + 2][lr] = av.z; As[lk + 3][lr] = av.w;
        Bs[lk + 0][lr] = bv.x; Bs[lk + 1][lr] = bv.y;
        Bs[lk + 2][lr] = bv.z; Bs[lk + 3][lr] = bv.w;
        __syncthreads();

        #pragma unroll
        for (int k = 0; k < BK; k++) {
            float a[8], b[8];
            *(float4*)(a)     = *(const float4*)&As[k][trow];
            *(float4*)(a + 4) = *(const float4*)&As[k][trow + 4];
            *(float4*)(b)     = *(const float4*)&Bs[k][tcol];
            *(float4*)(b + 4) = *(const float4*)&Bs[k][tcol + 4];
            #pragma unroll
            for (int i = 0; i < 8; i++)
                #pragma unroll
                for (int j = 0; j < 8; j++)
                    acc[i][j] += a[i] * b[j];
        }
    }

    float cnv[8];
    #pragma unroll
    for (int j = 0; j < 8; j++) cnv[j] = g_cn[bcol + tcol + j];

    #pragma unroll
    for (int i = 0; i < 8; i++) {
        int grow = brow + trow + i;
        bool rowok = (grow < N);
        float rnv = rowok ? g_rn[grow] : 0.f;
        float dv[8];
        unsigned long long best = ~0ull;
        #pragma unroll
        for (int j = 0; j < 8; j++) {
            float sq = rnv + cnv[j] - 2.0f * acc[i][j];
            float d = sqrtf(fmaxf(sq, 0.f));
            dv[j] = d;
            unsigned long long key =
                ((unsigned long long)__float_as_uint(d) << 32) |
                (unsigned long long)(unsigned)(bcol + tcol + j);
            best = (key < best) ? key : best;
        }
        best_sh[trow + i][tid & 15] = best;
        if (rowok && out) {
            float* orow = out + (size_t)grow * C + bcol + tcol;
            *(float4*)(orow)     = *(const float4*)(dv);
            *(float4*)(orow + 4) = *(const float4*)(dv + 4);
        }
    }
    __syncthreads();

    if (tid < BM) {
        int grow = brow + tid;
        if (grow < N) {
            unsigned long long best = best_sh[tid][0];
            #pragma unroll
            for (int j = 1; j < 16; j++) {
                unsigned long long k = best_sh[tid][j];
                best = (k < best) ? k : best;
            }
            g_cand[(size_t)grow * NCB + blockIdx.x] = best;
        }
    }
}

// ---------------------------------------------------------------------------
// Final pass: reduce 8 col-block candidates, cells output + winner-gated scatter.
__global__ void scatter_kernel(const int* __restrict__ nodes,
                               const float* __restrict__ times,
                               float* __restrict__ out_cells,
                               float* __restrict__ out_ncell,
                               float* __restrict__ out_ntime, int n, int m) {
    int i = blockIdx.x * blockDim.x + threadIdx.x;
    if (i >= n) return;
    const unsigned long long* cand = &g_cand[(size_t)i * NCB];
    unsigned long long best = cand[0];
    #pragma unroll
    for (int cb = 1; cb < NCB; cb++) {
        unsigned long long k = cand[cb];
        best = (k < best) ? k : best;
    }
    int cell = (int)(unsigned)(best & 0xFFFFFFFFull);
    if (out_cells) out_cells[i] = (float)cell;
    int nd = nodes[i];
    if (nd >= 0 && nd < m && g_winner[nd] == i) {
        if (out_ncell) out_ncell[nd] = (float)cell;
        if (out_ntime) out_ntime[nd] = times[i];
    }
}

// ---------------------------------------------------------------------------
extern "C" void kernel_launch(void* const* d_in, const int* in_sizes, int n_in,
                              void* d_out, int out_size) {
    const float* emb       = (const float*)d_in[0];   // [N, D]
    const float* mmap      = (const float*)d_in[1];   // [C, D]
    const int*   nodes     = (const int*)d_in[2];     // [N] (jax demotes int64->int32)
    const float* times     = (const float*)d_in[3];   // [N]
    const int*   node_cell = (const int*)d_in[4];     // [NUM_NODES]
    const float* node_time = (const float*)d_in[5];   // [NUM_NODES]

    const int D = 128;
    const int N = in_sizes[0] / D;       // 100000
    const int C = in_sizes[1] / D;       // 1024
    const int M = in_sizes[4];           // 1000000

    // Output layout = reference return order, but NEVER write past out_size.
    size_t have = (size_t)out_size;
    size_t nc = (size_t)N * C;
    float* base = (float*)d_out;
    float* out_dist  = (have >= nc) ? base : nullptr;
    float* out_cells = (have >= nc + (size_t)N) ? base + nc : nullptr;
    float* out_ncell = (have >= nc + N + (size_t)M) ? base + nc + N : nullptr;
    float* out_ntime = (have >= nc + N + 2ull * M) ? base + nc + N + M : nullptr;

    // 1. clear winner table
    clear_kernel<<<(M + 255) / 256, 256>>>(M);
    // 2. norms
    rownorm_kernel<<<(N * 32 + 255) / 256, 256>>>(emb, N, D, 0);
    rownorm_kernel<<<(C * 32 + 255) / 256, 256>>>(mmap, C, D, 1);
    // 3. copy node tables to output
    if (out_ncell || out_ntime)
        copy_tables_kernel<<<(M + 255) / 256, 256>>>(node_cell, node_time,
                                                     out_ncell, out_ntime, M);
    // 4. duplicate resolution (last index wins)
    winner_kernel<<<(N + 255) / 256, 256>>>(nodes, N, M);
    // 5. distance GEMM + argmin candidates
    {
        dim3 grid(C / BN, (N + BM - 1) / BM);
        gemm_dist_kernel<<<grid, 256>>>(emb, mmap, out_dist, N, C, D);
    }
    // 6. reduce candidates + cells + scatter
    scatter_kernel<<<(N + 255) / 256, 256>>>(nodes, times, out_cells,
                                             out_ncell, out_ntime, N, M);
}

// round 5
// speedup vs baseline: 1.4889x; 1.4889x over previous
#include <cuda_runtime.h>
#include <cuda_bf16.h>
#include <math.h>
#include <stdint.h>

// Problem constants: N=100000, D=128, C=1024, NUM_NODES=1e6.
#define MAX_N     100000
#define MAX_NODES 1000000
#define NCB       8            // C / BN column blocks

// Device scratch (no allocs allowed). NO 64-bit atomics (sm_103a trap).
__device__ unsigned long long g_cand[(size_t)(MAX_N + 128) * NCB];
__device__ int   g_winner[MAX_NODES];
__device__ float g_rn[MAX_N];
__device__ float g_cn[2048];

// ---------------------------------------------------------------------------
__global__ void clear_kernel(int m) {
    int i = blockIdx.x * blockDim.x + threadIdx.x;
    if (i < m) g_winner[i] = -1;
}

__global__ void rownorm_kernel(const float* __restrict__ X, int n, int D, int is_col) {
    int warp = (blockIdx.x * blockDim.x + threadIdx.x) >> 5;
    int lane = threadIdx.x & 31;
    if (warp >= n) return;
    const float* row = X + (size_t)warp * D;
    float s = 0.f;
    for (int k = lane; k < D; k += 32) { float v = row[k]; s += v * v; }
    #pragma unroll
    for (int o = 16; o; o >>= 1) s += __shfl_xor_sync(0xFFFFFFFFu, s, o);
    if (lane == 0) { if (is_col) g_cn[warp] = s; else g_rn[warp] = s; }
}

__global__ void copy_tables_kernel(const int* __restrict__ node_cell,
                                   const float* __restrict__ node_time,
                                   float* __restrict__ out_ncell,
                                   float* __restrict__ out_ntime, int m) {
    int j = blockIdx.x * blockDim.x + threadIdx.x;
    if (j < m) {
        if (out_ncell) out_ncell[j] = (float)node_cell[j];
        if (out_ntime) out_ntime[j] = node_time[j];
    }
}

__global__ void winner_kernel(const int* __restrict__ nodes, int n, int m) {
    int i = blockIdx.x * blockDim.x + threadIdx.x;
    if (i >= n) return;
    int nd = nodes[i];
    if (nd >= 0 && nd < m) atomicMax(&g_winner[nd], i);
}

// ---------------------------------------------------------------------------
// Tensor-core distance GEMM: 3xTF32 (hi*hi + hi*lo + lo*hi) == fp32 accuracy.
// Block tile 128x128, 8 warps in 2(M) x 4(N), each warp 64x32, BK=32.
#define BM 128
#define BN 128
#define BK 32
#define PAD 4      // 4-float pad keeps 16B alignment of every row (stride 144B)

// fp32 -> (tf32_hi rounded, lo residual as raw fp32; HW truncates to tf32)
__device__ __forceinline__ void split_tf32(float x, uint32_t& hi, uint32_t& lo) {
    uint32_t xb = __float_as_uint(x);
    uint32_t h  = (xb + 0x1000u) & 0xFFFFE000u;   // round-to-nearest tf32
    hi = h;
    lo = __float_as_uint(x - __uint_as_float(h));
}

__device__ __forceinline__ void mma_tf32(float* c, const uint32_t* a, const uint32_t* b) {
    asm volatile(
        "mma.sync.aligned.m16n8k8.row.col.f32.tf32.tf32.f32 "
        "{%0,%1,%2,%3}, {%4,%5,%6,%7}, {%8,%9}, {%0,%1,%2,%3};\n"
        : "+f"(c[0]), "+f"(c[1]), "+f"(c[2]), "+f"(c[3])
        : "r"(a[0]), "r"(a[1]), "r"(a[2]), "r"(a[3]), "r"(b[0]), "r"(b[1]));
}

__global__ __launch_bounds__(256, 2)
void gemm_dist_tc(const float* __restrict__ A,   // [N, 128]
                  const float* __restrict__ B,   // [1024, 128]
                  float* __restrict__ out,       // [N, 1024] (may be null)
                  int N, int C, int D) {
    __shared__ float As[BM][BK + PAD];                // [m][k]
    __shared__ float Bs[BN][BK + PAD];                // [n][k]
    __shared__ unsigned long long best_sh[BM][4];     // per-row per-warpN best key

    const int tid   = threadIdx.x;
    const int lane  = tid & 31;
    const int warp  = tid >> 5;
    const int warpM = warp >> 2;       // 0..1
    const int warpN = warp & 3;        // 0..3
    const int brow  = blockIdx.y * BM;
    const int bcol  = blockIdx.x * BN;
    const int g     = lane >> 2;       // groupID 0..7
    const int q     = lane & 3;        // quad lane 0..3

    float acc[4][4][4];                // [mtile][ntile][reg]
    #pragma unroll
    for (int mt = 0; mt < 4; mt++)
        #pragma unroll
        for (int nt = 0; nt < 4; nt++)
            #pragma unroll
            for (int r = 0; r < 4; r++) acc[mt][nt][r] = 0.f;

    // Loader mapping: 256 threads, each 4 float4 per tile.
    const int lrow = tid >> 3;          // 0..31
    const int lk4  = (tid & 7) * 4;     // 0..28

    for (int kc = 0; kc < 4; kc++) {
        const int k0 = kc * BK;
        float4 av[4], bv[4];
        #pragma unroll
        for (int i = 0; i < 4; i++) {
            int ar = min(brow + lrow + i * 32, N - 1);
            av[i] = *(const float4*)(A + (size_t)ar * D + k0 + lk4);
            bv[i] = *(const float4*)(B + (size_t)(bcol + lrow + i * 32) * D + k0 + lk4);
        }
        __syncthreads();
        #pragma unroll
        for (int i = 0; i < 4; i++) {
            *(float4*)&As[lrow + i * 32][lk4] = av[i];
            *(float4*)&Bs[lrow + i * 32][lk4] = bv[i];
        }
        __syncthreads();

        #pragma unroll
        for (int kk = 0; kk < 4; kk++) {
            const int kb = kk * 8;
            // A fragments for 4 m-tiles (m16n8k8 row-major layout)
            uint32_t ah[4][4], al[4][4];
            #pragma unroll
            for (int mt = 0; mt < 4; mt++) {
                int r0 = warpM * 64 + mt * 16 + g;
                split_tf32(As[r0    ][kb + q    ], ah[mt][0], al[mt][0]);
                split_tf32(As[r0 + 8][kb + q    ], ah[mt][1], al[mt][1]);
                split_tf32(As[r0    ][kb + q + 4], ah[mt][2], al[mt][2]);
                split_tf32(As[r0 + 8][kb + q + 4], ah[mt][3], al[mt][3]);
            }
            #pragma unroll
            for (int nt = 0; nt < 4; nt++) {
                int n0 = warpN * 32 + nt * 8 + g;
                uint32_t bh[2], bl[2];
                split_tf32(Bs[n0][kb + q    ], bh[0], bl[0]);
                split_tf32(Bs[n0][kb + q + 4], bh[1], bl[1]);
                #pragma unroll
                for (int mt = 0; mt < 4; mt++) {
                    mma_tf32(acc[mt][nt], ah[mt], bh);
                    mma_tf32(acc[mt][nt], ah[mt], bl);
                    mma_tf32(acc[mt][nt], al[mt], bh);
                }
            }
        }
    }

    // Epilogue: distances + per-row argmin keys.
    // C layout m16n8: c0,c1 -> row g, cols q*2, q*2+1 ; c2,c3 -> row g+8.
    float cn0[4], cn1[4];
    #pragma unroll
    for (int nt = 0; nt < 4; nt++) {
        int col = bcol + warpN * 32 + nt * 8 + q * 2;
        cn0[nt] = g_cn[col];
        cn1[nt] = g_cn[col + 1];
    }

    #pragma unroll
    for (int mt = 0; mt < 4; mt++) {
        #pragma unroll
        for (int half = 0; half < 2; half++) {
            int rloc = warpM * 64 + mt * 16 + g + half * 8;
            int grow = brow + rloc;
            bool rowok = (grow < N);
            float rn = rowok ? g_rn[grow] : 0.f;
            unsigned long long best = ~0ull;
            #pragma unroll
            for (int nt = 0; nt < 4; nt++) {
                int col = bcol + warpN * 32 + nt * 8 + q * 2;
                float d0 = sqrtf(fmaxf(rn + cn0[nt] - 2.0f * acc[mt][nt][half * 2 + 0], 0.f));
                float d1 = sqrtf(fmaxf(rn + cn1[nt] - 2.0f * acc[mt][nt][half * 2 + 1], 0.f));
                unsigned long long k0 =
                    ((unsigned long long)__float_as_uint(d0) << 32) | (unsigned)col;
                unsigned long long k1 =
                    ((unsigned long long)__float_as_uint(d1) << 32) | (unsigned)(col + 1);
                best = (k0 < best) ? k0 : best;
                best = (k1 < best) ? k1 : best;
                if (rowok && out) {
                    float2 dv = make_float2(d0, d1);
                    *(float2*)(out + (size_t)grow * C + col) = dv;
                }
            }
            // reduce across quad (lanes sharing this row)
            #pragma unroll
            for (int o = 1; o <= 2; o <<= 1) {
                unsigned long long other = __shfl_xor_sync(0xFFFFFFFFu, best, o);
                best = (other < best) ? other : best;
            }
            if (q == 0) best_sh[rloc][warpN] = best;
        }
    }
    __syncthreads();

    if (tid < BM) {
        int grow = brow + tid;
        if (grow < N) {
            unsigned long long best = best_sh[tid][0];
            #pragma unroll
            for (int j = 1; j < 4; j++) {
                unsigned long long k = best_sh[tid][j];
                best = (k < best) ? k : best;
            }
            g_cand[(size_t)grow * NCB + blockIdx.x] = best;
        }
    }
}

// ---------------------------------------------------------------------------
__global__ void scatter_kernel(const int* __restrict__ nodes,
                               const float* __restrict__ times,
                               float* __restrict__ out_cells,
                               float* __restrict__ out_ncell,
                               float* __restrict__ out_ntime, int n, int m) {
    int i = blockIdx.x * blockDim.x + threadIdx.x;
    if (i >= n) return;
    const unsigned long long* cand = &g_cand[(size_t)i * NCB];
    unsigned long long best = cand[0];
    #pragma unroll
    for (int cb = 1; cb < NCB; cb++) {
        unsigned long long k = cand[cb];
        best = (k < best) ? k : best;
    }
    int cell = (int)(unsigned)(best & 0xFFFFFFFFull);
    if (out_cells) out_cells[i] = (float)cell;
    int nd = nodes[i];
    if (nd >= 0 && nd < m && g_winner[nd] == i) {
        if (out_ncell) out_ncell[nd] = (float)cell;
        if (out_ntime) out_ntime[nd] = times[i];
    }
}

// ---------------------------------------------------------------------------
extern "C" void kernel_launch(void* const* d_in, const int* in_sizes, int n_in,
                              void* d_out, int out_size) {
    const float* emb       = (const float*)d_in[0];   // [N, D]
    const float* mmap      = (const float*)d_in[1];   // [C, D]
    const int*   nodes     = (const int*)d_in[2];     // [N] (jax demotes int64->int32)
    const float* times     = (const float*)d_in[3];   // [N]
    const int*   node_cell = (const int*)d_in[4];     // [NUM_NODES]
    const float* node_time = (const float*)d_in[5];   // [NUM_NODES]

    const int D = 128;
    const int N = in_sizes[0] / D;       // 100000
    const int C = in_sizes[1] / D;       // 1024
    const int M = in_sizes[4];           // 1000000

    size_t have = (size_t)out_size;
    size_t nc = (size_t)N * C;
    float* base = (float*)d_out;
    float* out_dist  = (have >= nc) ? base : nullptr;
    float* out_cells = (have >= nc + (size_t)N) ? base + nc : nullptr;
    float* out_ncell = (have >= nc + N + (size_t)M) ? base + nc + N : nullptr;
    float* out_ntime = (have >= nc + N + 2ull * M) ? base + nc + N + M : nullptr;

    clear_kernel<<<(M + 255) / 256, 256>>>(M);
    rownorm_kernel<<<(N * 32 + 255) / 256, 256>>>(emb, N, D, 0);
    rownorm_kernel<<<(C * 32 + 255) / 256, 256>>>(mmap, C, D, 1);
    if (out_ncell || out_ntime)
        copy_tables_kernel<<<(M + 255) / 256, 256>>>(node_cell, node_time,
                                                     out_ncell, out_ntime, M);
    winner_kernel<<<(N + 255) / 256, 256>>>(nodes, N, M);
    {
        dim3 grid(C / BN, (N + BM - 1) / BM);
        gemm_dist_tc<<<grid, 256>>>(emb, mmap, out_dist, N, C, D);
    }
    scatter_kernel<<<(N + 255) / 256, 256>>>(nodes, times, out_cells,
                                             out_ncell, out_ntime, N, M);
}